// round 1
// baseline (speedup 1.0000x reference)
#include <cuda_runtime.h>
#include <cuda_bf16.h>
#include <cstdint>

// Problem constants (fixed shapes for this problem instance)
constexpr int HID   = 256;
constexpr int NROWS = 5151;   // mesh points
constexpr int B     = 8;
constexpr int T     = 2048;
constexpr int NLAYERS = 3;

// Density kernel tiling: 36 rows/block -> ceil(5151/36)=144 blocks (~1/SM)
constexpr int RB      = 36;
constexpr int DB_BLKS = (NROWS + RB - 1) / RB;   // 144

// Scan tiling: 64 threads (2 warps) per block, 81 n-chunks x 8 batches
constexpr int SCAN_TPB = 64;
constexpr int NCHUNK   = (NROWS + SCAN_TPB - 1) / SCAN_TPB;  // 81
constexpr int NWB      = NCHUNK * (SCAN_TPB / 32);           // 162 warp-slots per batch

// Output section offsets (tuple flattened in order):
// b_norm[8,2048] | density_b[8,5151] | m[8,2048] | initial_states[8,5151] | mesh_b[8,5151,2]
constexpr int OFF_BNORM = 0;
constexpr int OFF_DENSB = 16384;
constexpr int OFF_M     = 57592;
constexpr int OFF_IS    = 73976;
constexpr int OFF_MESHB = 115184;
// total = 197600

// Scratch (device globals -- no allocation allowed)
__device__ float g_density[DB_BLKS * RB];          // padded density
__device__ float g_inv_sum;                        // 1 / sum(density)
__device__ float g_part[(size_t)B * NWB * T];      // per-warp partial dot products (~10.6 MB)

// ---------------------------------------------------------------------------
// Kernel 1: density MLP.  h stored TRANSPOSED in smem as [feature k][row r]
// so the k-loop inner body is: 1 coalesced LDG of W[k][j] + broadcast LDS.128
// of 36 h values + 36 FFMA.  In-place buffer (36 KB < 48 KB static limit),
// two syncthreads per layer.
// ---------------------------------------------------------------------------
__global__ __launch_bounds__(HID) void density_kernel(
    const float* __restrict__ mesh, const float* __restrict__ Win,
    const float* __restrict__ bin,  const float* __restrict__ Wblk,
    const float* __restrict__ bblk, const float* __restrict__ Wout,
    const float* __restrict__ bout)
{
    __shared__ float cur[HID * RB];   // [k][r], 36 KB
    const int j    = threadIdx.x;     // feature/column owned by this thread
    const int row0 = blockIdx.x * RB;

    float hcur[RB];

    // ---- input layer: h = relu(mesh @ W_in + b_in) ----
    {
        const float w0 = Win[j];
        const float w1 = Win[HID + j];
        const float bj = bin[j];
        #pragma unroll
        for (int r = 0; r < RB; r++) {
            const int rr = row0 + r;
            float m0 = 0.f, m1 = 0.f;
            if (rr < NROWS) { m0 = mesh[2 * rr]; m1 = mesh[2 * rr + 1]; }
            float v = fmaf(m1, w1, fmaf(m0, w0, bj));
            hcur[r] = fmaxf(v, 0.f);
        }
    }
    #pragma unroll
    for (int r = 0; r < RB; r += 4)
        *reinterpret_cast<float4*>(cur + j * RB + r) =
            make_float4(hcur[r], hcur[r + 1], hcur[r + 2], hcur[r + 3]);
    __syncthreads();

    // ---- residual layers: h = h + relu(h @ W + b) ----
    for (int l = 0; l < NLAYERS; l++) {
        const float* W  = Wblk + (size_t)l * HID * HID + j;
        const float  bl = bblk[l * HID + j];
        float acc[RB];
        #pragma unroll
        for (int r = 0; r < RB; r++) acc[r] = 0.f;

        #pragma unroll 2
        for (int k = 0; k < HID; k++) {
            const float w = W[(size_t)k * HID];           // coalesced across j, L2-resident
            const float4* hp = reinterpret_cast<const float4*>(cur + k * RB);
            #pragma unroll
            for (int q = 0; q < RB / 4; q++) {
                float4 h4 = hp[q];                        // broadcast LDS.128
                acc[4 * q + 0] = fmaf(h4.x, w, acc[4 * q + 0]);
                acc[4 * q + 1] = fmaf(h4.y, w, acc[4 * q + 1]);
                acc[4 * q + 2] = fmaf(h4.z, w, acc[4 * q + 2]);
                acc[4 * q + 3] = fmaf(h4.w, w, acc[4 * q + 3]);
            }
        }
        #pragma unroll
        for (int r = 0; r < RB; r++)
            hcur[r] += fmaxf(acc[r] + bl, 0.f);

        __syncthreads();   // everyone done reading cur
        #pragma unroll
        for (int r = 0; r < RB; r += 4)
            *reinterpret_cast<float4*>(cur + j * RB + r) =
                make_float4(hcur[r], hcur[r + 1], hcur[r + 2], hcur[r + 3]);
        __syncthreads();
    }

    // ---- output layer: density = sigmoid(h @ W_out + b_out) ----
    {
        const float wo = Wout[j];
        __syncthreads();   // (reads of cur above already fenced; keep ordering simple)
        #pragma unroll
        for (int r = 0; r < RB; r += 4)
            *reinterpret_cast<float4*>(cur + j * RB + r) =
                make_float4(hcur[r] * wo, hcur[r + 1] * wo, hcur[r + 2] * wo, hcur[r + 3] * wo);
        __syncthreads();
        if (j < RB) {
            float s0 = bout[0], s1 = 0.f, s2 = 0.f, s3 = 0.f;
            #pragma unroll 4
            for (int k = 0; k < HID; k += 4) {            // conflict-free: addrs k*RB + j
                s0 += cur[(k + 0) * RB + j];
                s1 += cur[(k + 1) * RB + j];
                s2 += cur[(k + 2) * RB + j];
                s3 += cur[(k + 3) * RB + j];
            }
            const float s  = (s0 + s1) + (s2 + s3);
            const int   rr = row0 + j;
            if (rr < NROWS)
                g_density[rr] = __fdividef(1.f, 1.f + __expf(-s));
        }
    }
}

// ---------------------------------------------------------------------------
// Kernel 2: 1/sum(density)  (single block, deterministic, no atomics)
// ---------------------------------------------------------------------------
__global__ __launch_bounds__(1024) void sum_kernel()
{
    __shared__ float sh[32];
    float s = 0.f;
    for (int i = threadIdx.x; i < NROWS; i += 1024) s += g_density[i];
    #pragma unroll
    for (int o = 16; o; o >>= 1) s += __shfl_xor_sync(0xffffffffu, s, o);
    if ((threadIdx.x & 31) == 0) sh[threadIdx.x >> 5] = s;
    __syncthreads();
    if (threadIdx.x < 32) {
        s = sh[threadIdx.x];
        #pragma unroll
        for (int o = 16; o; o >>= 1) s += __shfl_xor_sync(0xffffffffu, s, o);
        if (threadIdx.x == 0) g_inv_sum = __fdividef(1.f, s);
    }
}

// ---------------------------------------------------------------------------
// Kernel 3: Preisach scan fused with density dot-product.
// One thread = one mesh point; sequential over t; `inc` is uniform per (b,t)
// so only ONE sigmoid per point-step.  Per-warp shuffle reduce -> per-warp
// partial buffer (no block syncs inside the t-loop).
// ---------------------------------------------------------------------------
__global__ __launch_bounds__(SCAN_TPB) void scan_kernel(
    const float* __restrict__ dec, const float* __restrict__ s0_all,
    const float* __restrict__ y0,  const float* __restrict__ mesh)
{
    __shared__ float hs[T];
    const int b     = blockIdx.y;
    const int chunk = blockIdx.x;
    const int i     = chunk * SCAN_TPB + threadIdx.x;

    for (int t = threadIdx.x; t < T; t += SCAN_TPB) hs[t] = dec[b * T + t];

    float na = 0.f, nb = 0.f, d = 0.f, s = 0.f;
    if (i < NROWS) {
        nb = -mesh[2 * i] * 1000.f;       // -beta / TEMP
        na = -mesh[2 * i + 1] * 1000.f;   // -alpha / TEMP
        d  = g_density[i];
        s  = s0_all[b * NROWS + i];
    }
    __syncthreads();

    float hprev = y0[b];
    const int lane = threadIdx.x & 31;
    const int w    = threadIdx.x >> 5;
    float* mypart = g_part + ((size_t)(b * NWB + chunk * (SCAN_TPB / 32) + w)) * T;

    #pragma unroll 2
    for (int t = 0; t < T; t++) {
        const float ht  = hs[t];
        const bool  inc = (ht >= hprev);
        hprev = ht;
        const float x   = fmaf(ht, 1000.f, inc ? na : nb);       // (ht - thr)/TEMP
        const float sig = __fdividef(1.f, 1.f + __expf(-x));
        s = inc ? fmaf(1.f - s, sig, s)      // s + (1-s)*up
                : fmaf(1.f + s, sig, -1.f);  // -1 + (s+1)*dn
        float c = d * s;
        #pragma unroll
        for (int o = 16; o; o >>= 1) c += __shfl_xor_sync(0xffffffffu, c, o);
        if (lane == 0) mypart[t] = c;
    }
}

// ---------------------------------------------------------------------------
// Kernel 4: reduce warp partials -> m, b_norm
// ---------------------------------------------------------------------------
__global__ __launch_bounds__(256) void finalize_kernel(float* __restrict__ out)
{
    const int idx = blockIdx.x * blockDim.x + threadIdx.x;
    if (idx >= B * T) return;
    const int b = idx / T;
    const int t = idx - b * T;
    const float* p = g_part + (size_t)b * NWB * T + t;   // stride T between slots, coalesced in t
    float s0 = 0.f, s1 = 0.f;
    #pragma unroll 2
    for (int wv = 0; wv < NWB; wv += 2) {
        s0 += p[(size_t)wv * T];
        s1 += p[(size_t)(wv + 1) * T];
    }
    const float m = (s0 + s1) * g_inv_sum;
    out[OFF_BNORM + idx] = fmaf(0.5f, m, 0.5f);   // H_SCALE=0, M_SCALE=0.5, M_OFFSET=0.5
    out[OFF_M + idx]     = m;
}

// ---------------------------------------------------------------------------
// Kernel 5: broadcast / passthrough sections
// ---------------------------------------------------------------------------
__global__ __launch_bounds__(256) void fill_kernel(
    const float* __restrict__ s0_all, const float* __restrict__ mesh,
    float* __restrict__ out)
{
    const int i = blockIdx.x * blockDim.x + threadIdx.x;
    if (i < B * NROWS) {
        out[OFF_DENSB + i] = g_density[i % NROWS];   // density broadcast
        out[OFF_IS + i]    = s0_all[i];              // initial_states passthrough
    }
    if (i < B * NROWS * 2)
        out[OFF_MESHB + i] = mesh[i % (2 * NROWS)];  // mesh broadcast
}

// ---------------------------------------------------------------------------
extern "C" void kernel_launch(void* const* d_in, const int* in_sizes, int n_in,
                              void* d_out, int out_size)
{
    (void)in_sizes; (void)n_in; (void)out_size;
    // metadata order: encoder_input, decoder_input, initial_states, y0, mesh,
    //                 W_in, b_in, W_blk, b_blk, W_out, b_out
    const float* dec  = (const float*)d_in[1];
    const float* init = (const float*)d_in[2];
    const float* y0   = (const float*)d_in[3];
    const float* mesh = (const float*)d_in[4];
    const float* Win  = (const float*)d_in[5];
    const float* bin  = (const float*)d_in[6];
    const float* Wblk = (const float*)d_in[7];
    const float* bblk = (const float*)d_in[8];
    const float* Wout = (const float*)d_in[9];
    const float* bout = (const float*)d_in[10];
    float* out = (float*)d_out;

    density_kernel<<<DB_BLKS, HID>>>(mesh, Win, bin, Wblk, bblk, Wout, bout);
    sum_kernel<<<1, 1024>>>();
    fill_kernel<<<(B * NROWS * 2 + 255) / 256, 256>>>(init, mesh, out);
    scan_kernel<<<dim3(NCHUNK, B), SCAN_TPB>>>(dec, init, y0, mesh);
    finalize_kernel<<<(B * T + 255) / 256, 256>>>(out);
}

// round 2
// speedup vs baseline: 1.5509x; 1.5509x over previous
#include <cuda_runtime.h>
#include <cuda_bf16.h>
#include <cstdint>

// Problem constants
constexpr int HID   = 256;
constexpr int NROWS = 5151;
constexpr int B     = 8;
constexpr int T     = 2048;
constexpr int NLAYERS = 3;

// Density kernel tiling
constexpr int RB      = 36;
constexpr int DB_BLKS = (NROWS + RB - 1) / RB;   // 144

// Chunked scan config
constexpr int C   = 8;            // time chunks
constexpr int TC  = T / C;        // 256 steps per chunk
constexpr int P1_TPB = 128;       // pass1 threads (1 point each)
constexpr int P1_BLK = (NROWS + P1_TPB - 1) / P1_TPB;   // 41
constexpr int P2_TPB = 64;        // pass2 threads (2 warps)
constexpr int PPT    = 4;         // points per thread in pass2
constexpr int P2_PTS = P2_TPB * PPT;                     // 256 points per block
constexpr int P2_BLK = (NROWS + P2_PTS - 1) / P2_PTS;    // 21
constexpr int NW2    = P2_BLK * (P2_TPB / 32);           // 42 warp slots per batch

// Output section offsets
constexpr int OFF_BNORM = 0;
constexpr int OFF_DENSB = 16384;
constexpr int OFF_M     = 57592;
constexpr int OFF_IS    = 73976;
constexpr int OFF_MESHB = 115184;

// Scratch (device globals)
__device__ float  g_density[DB_BLKS * RB];
__device__ float  g_inv_sum;
__device__ float2 g_ab[(size_t)B * (C - 1) * NROWS];      // chunk affine transforms
__device__ float  g_sstart[(size_t)B * C * NROWS];        // chunk start states
__device__ float  g_part[(size_t)B * NW2 * T];            // per-warp partial dots

__device__ __forceinline__ float tanh_fast(float x) {
    float y;
    asm("tanh.approx.f32 %0, %1;" : "=f"(y) : "f"(x));
    return y;
}

// ---------------------------------------------------------------------------
// Kernel 1: density MLP (unchanged from R1 — revisit next round)
// ---------------------------------------------------------------------------
__global__ __launch_bounds__(HID) void density_kernel(
    const float* __restrict__ mesh, const float* __restrict__ Win,
    const float* __restrict__ bin,  const float* __restrict__ Wblk,
    const float* __restrict__ bblk, const float* __restrict__ Wout,
    const float* __restrict__ bout)
{
    __shared__ float cur[HID * RB];
    const int j    = threadIdx.x;
    const int row0 = blockIdx.x * RB;
    float hcur[RB];

    {
        const float w0 = Win[j];
        const float w1 = Win[HID + j];
        const float bj = bin[j];
        #pragma unroll
        for (int r = 0; r < RB; r++) {
            const int rr = row0 + r;
            float m0 = 0.f, m1 = 0.f;
            if (rr < NROWS) { m0 = mesh[2 * rr]; m1 = mesh[2 * rr + 1]; }
            hcur[r] = fmaxf(fmaf(m1, w1, fmaf(m0, w0, bj)), 0.f);
        }
    }
    #pragma unroll
    for (int r = 0; r < RB; r += 4)
        *reinterpret_cast<float4*>(cur + j * RB + r) =
            make_float4(hcur[r], hcur[r + 1], hcur[r + 2], hcur[r + 3]);
    __syncthreads();

    for (int l = 0; l < NLAYERS; l++) {
        const float* W  = Wblk + (size_t)l * HID * HID + j;
        const float  bl = bblk[l * HID + j];
        float acc[RB];
        #pragma unroll
        for (int r = 0; r < RB; r++) acc[r] = 0.f;

        #pragma unroll 2
        for (int k = 0; k < HID; k++) {
            const float w = W[(size_t)k * HID];
            const float4* hp = reinterpret_cast<const float4*>(cur + k * RB);
            #pragma unroll
            for (int q = 0; q < RB / 4; q++) {
                float4 h4 = hp[q];
                acc[4 * q + 0] = fmaf(h4.x, w, acc[4 * q + 0]);
                acc[4 * q + 1] = fmaf(h4.y, w, acc[4 * q + 1]);
                acc[4 * q + 2] = fmaf(h4.z, w, acc[4 * q + 2]);
                acc[4 * q + 3] = fmaf(h4.w, w, acc[4 * q + 3]);
            }
        }
        #pragma unroll
        for (int r = 0; r < RB; r++)
            hcur[r] += fmaxf(acc[r] + bl, 0.f);

        __syncthreads();
        #pragma unroll
        for (int r = 0; r < RB; r += 4)
            *reinterpret_cast<float4*>(cur + j * RB + r) =
                make_float4(hcur[r], hcur[r + 1], hcur[r + 2], hcur[r + 3]);
        __syncthreads();
    }

    {
        const float wo = Wout[j];
        #pragma unroll
        for (int r = 0; r < RB; r += 4)
            *reinterpret_cast<float4*>(cur + j * RB + r) =
                make_float4(hcur[r] * wo, hcur[r + 1] * wo, hcur[r + 2] * wo, hcur[r + 3] * wo);
        __syncthreads();
        if (j < RB) {
            float s0 = bout[0], s1 = 0.f, s2 = 0.f, s3 = 0.f;
            #pragma unroll 4
            for (int k = 0; k < HID; k += 4) {
                s0 += cur[(k + 0) * RB + j];
                s1 += cur[(k + 1) * RB + j];
                s2 += cur[(k + 2) * RB + j];
                s3 += cur[(k + 3) * RB + j];
            }
            const float s  = (s0 + s1) + (s2 + s3);
            const int   rr = row0 + j;
            if (rr < NROWS)
                g_density[rr] = __fdividef(1.f, 1.f + __expf(-s));
        }
    }
}

// ---------------------------------------------------------------------------
// Kernel 2: 1/sum(density)
// ---------------------------------------------------------------------------
__global__ __launch_bounds__(1024) void sum_kernel()
{
    __shared__ float sh[32];
    float s = 0.f;
    for (int i = threadIdx.x; i < NROWS; i += 1024) s += g_density[i];
    #pragma unroll
    for (int o = 16; o; o >>= 1) s += __shfl_xor_sync(0xffffffffu, s, o);
    if ((threadIdx.x & 31) == 0) sh[threadIdx.x >> 5] = s;
    __syncthreads();
    if (threadIdx.x < 32) {
        s = sh[threadIdx.x];
        #pragma unroll
        for (int o = 16; o; o >>= 1) s += __shfl_xor_sync(0xffffffffu, s, o);
        if (threadIdx.x == 0) g_inv_sum = __fdividef(1.f, s);
    }
}

// ---------------------------------------------------------------------------
// Kernel 3 (pass 1): per-chunk composed affine transform (A,B) for chunks
// 0..C-2.  s' = a_t*s + b_t with a = fma(-c2,u,0.5), b = fma(0.5,u,c2),
// u = tanh((h-thr)*500), c2 = inc ? +0.5 : -0.5.
// ---------------------------------------------------------------------------
__global__ __launch_bounds__(P1_TPB) void pass1_kernel(
    const float* __restrict__ dec, const float* __restrict__ y0,
    const float* __restrict__ mesh)
{
    __shared__ float hs[TC];
    const int b  = blockIdx.z;
    const int ck = blockIdx.y;                 // chunk 0..C-2
    const int i  = blockIdx.x * P1_TPB + threadIdx.x;
    const int t0 = ck * TC;

    for (int t = threadIdx.x; t < TC; t += P1_TPB) hs[t] = dec[b * T + t0 + t];

    float na2 = 0.f, nb2 = 0.f;
    if (i < NROWS) {
        nb2 = -mesh[2 * i] * 500.f;       // -beta /(2*TEMP)
        na2 = -mesh[2 * i + 1] * 500.f;   // -alpha/(2*TEMP)
    }
    __syncthreads();

    float hprev = (ck == 0) ? y0[b] : dec[b * T + t0 - 1];
    float A = 1.f, Bc = 0.f;

    #pragma unroll 4
    for (int t = 0; t < TC; t++) {
        const float ht  = hs[t];
        const bool  inc = (ht >= hprev);
        hprev = ht;
        const float thr = inc ? na2 : nb2;
        const float c2  = inc ? 0.5f : -0.5f;
        const float u   = tanh_fast(fmaf(ht, 500.f, thr));
        const float a   = fmaf(-c2, u, 0.5f);
        const float bb  = fmaf(0.5f, u, c2);
        A  = A * a;
        Bc = fmaf(a, Bc, bb);
    }
    if (i < NROWS)
        g_ab[((size_t)b * (C - 1) + ck) * NROWS + i] = make_float2(A, Bc);
}

// ---------------------------------------------------------------------------
// Kernel 4: compose chunk transforms -> start state of each chunk
// ---------------------------------------------------------------------------
__global__ __launch_bounds__(256) void compose_kernel(const float* __restrict__ s0_all)
{
    const int idx = blockIdx.x * blockDim.x + threadIdx.x;
    if (idx >= B * NROWS) return;
    const int b = idx / NROWS;
    const int i = idx - b * NROWS;
    float s = s0_all[idx];
    g_sstart[((size_t)b * C + 0) * NROWS + i] = s;
    #pragma unroll
    for (int ck = 0; ck < C - 1; ck++) {
        const float2 ab = g_ab[((size_t)b * (C - 1) + ck) * NROWS + i];
        s = fmaf(ab.x, s, ab.y);
        g_sstart[((size_t)b * C + ck + 1) * NROWS + i] = s;
    }
}

// ---------------------------------------------------------------------------
// Kernel 5 (pass 2): replay each chunk, fused density dot.  PPT=4 points
// per thread (ILP + 4x fewer shuffles per point-step).
// ---------------------------------------------------------------------------
__global__ __launch_bounds__(P2_TPB) void pass2_kernel(
    const float* __restrict__ dec, const float* __restrict__ y0,
    const float* __restrict__ mesh)
{
    __shared__ float hs[TC];
    const int b   = blockIdx.z;
    const int ck  = blockIdx.y;
    const int t0  = ck * TC;
    const int i0  = blockIdx.x * P2_PTS;      // block's first point
    const int w   = threadIdx.x >> 5;
    const int lane= threadIdx.x & 31;

    for (int t = threadIdx.x; t < TC; t += P2_TPB) hs[t] = dec[b * T + t0 + t];

    float na2[PPT], nb2[PPT], d[PPT], s[PPT];
    #pragma unroll
    for (int p = 0; p < PPT; p++) {
        const int i = i0 + w * (32 * PPT) + p * 32 + lane;   // warp covers 128 contiguous pts
        if (i < NROWS) {
            nb2[p] = -mesh[2 * i] * 500.f;
            na2[p] = -mesh[2 * i + 1] * 500.f;
            d[p]   = g_density[i];
            s[p]   = g_sstart[((size_t)b * C + ck) * NROWS + i];
        } else { nb2[p] = 0.f; na2[p] = 0.f; d[p] = 0.f; s[p] = 0.f; }
    }
    __syncthreads();

    float hprev = (ck == 0) ? y0[b] : dec[b * T + t0 - 1];
    float* mypart = g_part + ((size_t)(b * NW2 + blockIdx.x * 2 + w)) * T + t0;

    #pragma unroll 2
    for (int t = 0; t < TC; t++) {
        const float ht  = hs[t];
        const bool  inc = (ht >= hprev);
        hprev = ht;
        const float c2  = inc ? 0.5f : -0.5f;
        float acc = 0.f;
        #pragma unroll
        for (int p = 0; p < PPT; p++) {
            const float thr = inc ? na2[p] : nb2[p];
            const float u   = tanh_fast(fmaf(ht, 500.f, thr));
            const float a   = fmaf(-c2, u, 0.5f);
            const float bb  = fmaf(0.5f, u, c2);
            s[p] = fmaf(a, s[p], bb);
            acc  = fmaf(d[p], s[p], acc);
        }
        #pragma unroll
        for (int o = 16; o; o >>= 1) acc += __shfl_xor_sync(0xffffffffu, acc, o);
        if (lane == 0) mypart[t] = acc;
    }
}

// ---------------------------------------------------------------------------
// Kernel 6: reduce warp partials -> m, b_norm
// ---------------------------------------------------------------------------
__global__ __launch_bounds__(256) void finalize_kernel(float* __restrict__ out)
{
    const int idx = blockIdx.x * blockDim.x + threadIdx.x;
    if (idx >= B * T) return;
    const int b = idx / T;
    const int t = idx - b * T;
    const float* p = g_part + (size_t)b * NW2 * T + t;
    float s0 = 0.f, s1 = 0.f;
    #pragma unroll 2
    for (int wv = 0; wv < NW2; wv += 2) {
        s0 += p[(size_t)wv * T];
        s1 += p[(size_t)(wv + 1) * T];
    }
    const float m = (s0 + s1) * g_inv_sum;
    out[OFF_BNORM + idx] = fmaf(0.5f, m, 0.5f);
    out[OFF_M + idx]     = m;
}

// ---------------------------------------------------------------------------
// Kernel 7: broadcast / passthrough sections
// ---------------------------------------------------------------------------
__global__ __launch_bounds__(256) void fill_kernel(
    const float* __restrict__ s0_all, const float* __restrict__ mesh,
    float* __restrict__ out)
{
    const int i = blockIdx.x * blockDim.x + threadIdx.x;
    if (i < B * NROWS) {
        out[OFF_DENSB + i] = g_density[i % NROWS];
        out[OFF_IS + i]    = s0_all[i];
    }
    if (i < B * NROWS * 2)
        out[OFF_MESHB + i] = mesh[i % (2 * NROWS)];
}

// ---------------------------------------------------------------------------
extern "C" void kernel_launch(void* const* d_in, const int* in_sizes, int n_in,
                              void* d_out, int out_size)
{
    (void)in_sizes; (void)n_in; (void)out_size;
    const float* dec  = (const float*)d_in[1];
    const float* init = (const float*)d_in[2];
    const float* y0   = (const float*)d_in[3];
    const float* mesh = (const float*)d_in[4];
    const float* Win  = (const float*)d_in[5];
    const float* bin  = (const float*)d_in[6];
    const float* Wblk = (const float*)d_in[7];
    const float* bblk = (const float*)d_in[8];
    const float* Wout = (const float*)d_in[9];
    const float* bout = (const float*)d_in[10];
    float* out = (float*)d_out;

    density_kernel<<<DB_BLKS, HID>>>(mesh, Win, bin, Wblk, bblk, Wout, bout);
    pass1_kernel<<<dim3(P1_BLK, C - 1, B), P1_TPB>>>(dec, y0, mesh);
    sum_kernel<<<1, 1024>>>();
    fill_kernel<<<(B * NROWS * 2 + 255) / 256, 256>>>(init, mesh, out);
    compose_kernel<<<(B * NROWS + 255) / 256, 256>>>(init);
    pass2_kernel<<<dim3(P2_BLK, C, B), P2_TPB>>>(dec, y0, mesh);
    finalize_kernel<<<(B * T + 255) / 256, 256>>>(out);
}

// round 4
// speedup vs baseline: 2.0773x; 1.3394x over previous
#include <cuda_runtime.h>
#include <cuda_bf16.h>
#include <cstdint>

// Problem constants
constexpr int HID   = 256;
constexpr int NROWS = 5151;
constexpr int B     = 8;
constexpr int T     = 2048;
constexpr int NLAYERS = 3;

// Density kernel tiling
constexpr int RB      = 36;
constexpr int DB_BLKS = (NROWS + RB - 1) / RB;   // 144
constexpr int KU      = 8;                        // k-prefetch depth

// Chunked scan config
constexpr int C   = 8;            // time chunks
constexpr int TC  = T / C;        // 256 steps per chunk
constexpr int P1_TPB = 128;
constexpr int P1_BLK = (NROWS + P1_TPB - 1) / P1_TPB;   // 41
constexpr int P2_TPB = 64;
constexpr int PPT    = 4;
constexpr int P2_PTS = P2_TPB * PPT;                     // 256
constexpr int P2_BLK = (NROWS + P2_PTS - 1) / P2_PTS;    // 21
constexpr int NW2    = P2_BLK * (P2_TPB / 32);           // 42

// Output section offsets
constexpr int OFF_BNORM = 0;
constexpr int OFF_DENSB = 16384;
constexpr int OFF_M     = 57592;
constexpr int OFF_IS    = 73976;
constexpr int OFF_MESHB = 115184;

// Scratch (device globals)
__device__ float  g_density[DB_BLKS * RB];
__device__ float  g_inv_sum;
__device__ float2 g_ab[(size_t)B * (C - 1) * NROWS];
__device__ float  g_sstart[(size_t)B * C * NROWS];
__device__ float  g_part[(size_t)B * NW2 * T];

typedef unsigned long long u64;

__device__ __forceinline__ float tanh_fast(float x) {
    float y;
    asm("tanh.approx.f32 %0, %1;" : "=f"(y) : "f"(x));
    return y;
}
__device__ __forceinline__ u64 pack2(float lo, float hi) {
    u64 r; asm("mov.b64 %0, {%1, %2};" : "=l"(r) : "f"(lo), "f"(hi)); return r;
}
__device__ __forceinline__ void unpack2(u64 v, float& lo, float& hi) {
    asm("mov.b64 {%0, %1}, %2;" : "=f"(lo), "=f"(hi) : "l"(v));
}
__device__ __forceinline__ u64 fma2(u64 a, u64 b, u64 c) {
    u64 d; asm("fma.rn.f32x2 %0, %1, %2, %3;" : "=l"(d) : "l"(a), "l"(b), "l"(c)); return d;
}

// ---------------------------------------------------------------------------
// Kernel 1: density MLP.  h kept TRANSPOSED in smem as [k][r].  Inner loop:
// KU=8 software-pipelined weight prefetch (hides L2 latency) + packed
// fma.rn.f32x2 (FFMA2: 18 packed FMAs replace 36 scalar FFMA per k).
// ---------------------------------------------------------------------------
__global__ __launch_bounds__(HID) void density_kernel(
    const float* __restrict__ mesh, const float* __restrict__ Win,
    const float* __restrict__ bin,  const float* __restrict__ Wblk,
    const float* __restrict__ bblk, const float* __restrict__ Wout,
    const float* __restrict__ bout)
{
    __shared__ float cur[HID * RB];   // [k][r], 36 KB, 16B-aligned rows (144B)
    const int j    = threadIdx.x;
    const int row0 = blockIdx.x * RB;
    float hcur[RB];

    // ---- input layer ----
    {
        const float w0 = Win[j];
        const float w1 = Win[HID + j];
        const float bj = bin[j];
        #pragma unroll
        for (int r = 0; r < RB; r++) {
            const int rr = row0 + r;
            float m0 = 0.f, m1 = 0.f;
            if (rr < NROWS) { m0 = mesh[2 * rr]; m1 = mesh[2 * rr + 1]; }
            hcur[r] = fmaxf(fmaf(m1, w1, fmaf(m0, w0, bj)), 0.f);
        }
    }
    #pragma unroll
    for (int r = 0; r < RB; r += 4)
        *reinterpret_cast<float4*>(cur + j * RB + r) =
            make_float4(hcur[r], hcur[r + 1], hcur[r + 2], hcur[r + 3]);
    __syncthreads();

    // ---- residual layers ----
    for (int l = 0; l < NLAYERS; l++) {
        const float* Wj = Wblk + (size_t)l * HID * HID + j;
        const float  bl = bblk[l * HID + j];

        u64 acc2[RB / 2];
        #pragma unroll
        for (int q = 0; q < RB / 2; q++) acc2[q] = 0ull;

        float wbuf[KU];
        #pragma unroll
        for (int kk = 0; kk < KU; kk++) wbuf[kk] = Wj[(size_t)kk * HID];

        #pragma unroll 1
        for (int k0 = 0; k0 < HID; k0 += KU) {
            float wn[KU];
            const bool more = (k0 + KU) < HID;
            #pragma unroll
            for (int kk = 0; kk < KU; kk++)
                wn[kk] = more ? Wj[(size_t)(k0 + KU + kk) * HID] : 0.f;

            #pragma unroll
            for (int kk = 0; kk < KU; kk++) {
                const u64 w2 = pack2(wbuf[kk], wbuf[kk]);
                const ulonglong2* hp =
                    reinterpret_cast<const ulonglong2*>(cur + (k0 + kk) * RB);
                #pragma unroll
                for (int q = 0; q < RB / 4; q++) {          // 9 LDS.128 per k
                    const ulonglong2 h2 = hp[q];
                    acc2[2 * q]     = fma2(h2.x, w2, acc2[2 * q]);
                    acc2[2 * q + 1] = fma2(h2.y, w2, acc2[2 * q + 1]);
                }
            }
            #pragma unroll
            for (int kk = 0; kk < KU; kk++) wbuf[kk] = wn[kk];
        }

        #pragma unroll
        for (int q = 0; q < RB / 2; q++) {
            float a0, a1;
            unpack2(acc2[q], a0, a1);
            hcur[2 * q]     += fmaxf(a0 + bl, 0.f);
            hcur[2 * q + 1] += fmaxf(a1 + bl, 0.f);
        }

        __syncthreads();
        #pragma unroll
        for (int r = 0; r < RB; r += 4)
            *reinterpret_cast<float4*>(cur + j * RB + r) =
                make_float4(hcur[r], hcur[r + 1], hcur[r + 2], hcur[r + 3]);
        __syncthreads();
    }

    // ---- output layer ----
    {
        const float wo = Wout[j];
        #pragma unroll
        for (int r = 0; r < RB; r += 4)
            *reinterpret_cast<float4*>(cur + j * RB + r) =
                make_float4(hcur[r] * wo, hcur[r + 1] * wo, hcur[r + 2] * wo, hcur[r + 3] * wo);
        __syncthreads();
        if (j < RB) {
            float s0 = bout[0], s1 = 0.f, s2 = 0.f, s3 = 0.f;
            #pragma unroll 4
            for (int k = 0; k < HID; k += 4) {
                s0 += cur[(k + 0) * RB + j];
                s1 += cur[(k + 1) * RB + j];
                s2 += cur[(k + 2) * RB + j];
                s3 += cur[(k + 3) * RB + j];
            }
            const float s  = (s0 + s1) + (s2 + s3);
            const int   rr = row0 + j;
            if (rr < NROWS)
                g_density[rr] = __fdividef(1.f, 1.f + __expf(-s));
        }
    }
}

// ---------------------------------------------------------------------------
// Kernel 2: 1/sum(density)
// ---------------------------------------------------------------------------
__global__ __launch_bounds__(1024) void sum_kernel()
{
    __shared__ float sh[32];
    float s = 0.f;
    for (int i = threadIdx.x; i < NROWS; i += 1024) s += g_density[i];
    #pragma unroll
    for (int o = 16; o; o >>= 1) s += __shfl_xor_sync(0xffffffffu, s, o);
    if ((threadIdx.x & 31) == 0) sh[threadIdx.x >> 5] = s;
    __syncthreads();
    if (threadIdx.x < 32) {
        s = sh[threadIdx.x];
        #pragma unroll
        for (int o = 16; o; o >>= 1) s += __shfl_xor_sync(0xffffffffu, s, o);
        if (threadIdx.x == 0) g_inv_sum = __fdividef(1.f, s);
    }
}

// ---------------------------------------------------------------------------
// Kernel 3 (pass 1): per-chunk composed affine transform
// ---------------------------------------------------------------------------
__global__ __launch_bounds__(P1_TPB) void pass1_kernel(
    const float* __restrict__ dec, const float* __restrict__ y0,
    const float* __restrict__ mesh)
{
    __shared__ float hs[TC];
    const int b  = blockIdx.z;
    const int ck = blockIdx.y;
    const int i  = blockIdx.x * P1_TPB + threadIdx.x;
    const int t0 = ck * TC;

    for (int t = threadIdx.x; t < TC; t += P1_TPB) hs[t] = dec[b * T + t0 + t];

    float na2 = 0.f, nb2 = 0.f;
    if (i < NROWS) {
        nb2 = -mesh[2 * i] * 500.f;
        na2 = -mesh[2 * i + 1] * 500.f;
    }
    __syncthreads();

    float hprev = (ck == 0) ? y0[b] : dec[b * T + t0 - 1];
    float A = 1.f, Bc = 0.f;

    #pragma unroll 4
    for (int t = 0; t < TC; t++) {
        const float ht  = hs[t];
        const bool  inc = (ht >= hprev);
        hprev = ht;
        const float thr = inc ? na2 : nb2;
        const float c2  = inc ? 0.5f : -0.5f;
        const float u   = tanh_fast(fmaf(ht, 500.f, thr));
        const float a   = fmaf(-c2, u, 0.5f);
        const float bb  = fmaf(0.5f, u, c2);
        A  = A * a;
        Bc = fmaf(a, Bc, bb);
    }
    if (i < NROWS)
        g_ab[((size_t)b * (C - 1) + ck) * NROWS + i] = make_float2(A, Bc);
}

// ---------------------------------------------------------------------------
// Kernel 4: compose chunk transforms -> chunk start states
// ---------------------------------------------------------------------------
__global__ __launch_bounds__(256) void compose_kernel(const float* __restrict__ s0_all)
{
    const int idx = blockIdx.x * blockDim.x + threadIdx.x;
    if (idx >= B * NROWS) return;
    const int b = idx / NROWS;
    const int i = idx - b * NROWS;
    float s = s0_all[idx];
    g_sstart[((size_t)b * C + 0) * NROWS + i] = s;
    #pragma unroll
    for (int ck = 0; ck < C - 1; ck++) {
        const float2 ab = g_ab[((size_t)b * (C - 1) + ck) * NROWS + i];
        s = fmaf(ab.x, s, ab.y);
        g_sstart[((size_t)b * C + ck + 1) * NROWS + i] = s;
    }
}

// ---------------------------------------------------------------------------
// Kernel 5 (pass 2): replay chunks, fused density dot
// ---------------------------------------------------------------------------
__global__ __launch_bounds__(P2_TPB) void pass2_kernel(
    const float* __restrict__ dec, const float* __restrict__ y0,
    const float* __restrict__ mesh)
{
    __shared__ float hs[TC];
    const int b   = blockIdx.z;
    const int ck  = blockIdx.y;
    const int t0  = ck * TC;
    const int i0  = blockIdx.x * P2_PTS;
    const int w   = threadIdx.x >> 5;
    const int lane= threadIdx.x & 31;

    for (int t = threadIdx.x; t < TC; t += P2_TPB) hs[t] = dec[b * T + t0 + t];

    float na2[PPT], nb2[PPT], d[PPT], s[PPT];
    #pragma unroll
    for (int p = 0; p < PPT; p++) {
        const int i = i0 + w * (32 * PPT) + p * 32 + lane;
        if (i < NROWS) {
            nb2[p] = -mesh[2 * i] * 500.f;
            na2[p] = -mesh[2 * i + 1] * 500.f;
            d[p]   = g_density[i];
            s[p]   = g_sstart[((size_t)b * C + ck) * NROWS + i];
        } else { nb2[p] = 0.f; na2[p] = 0.f; d[p] = 0.f; s[p] = 0.f; }
    }
    __syncthreads();

    float hprev = (ck == 0) ? y0[b] : dec[b * T + t0 - 1];
    float* mypart = g_part + ((size_t)(b * NW2 + blockIdx.x * 2 + w)) * T + t0;

    #pragma unroll 2
    for (int t = 0; t < TC; t++) {
        const float ht  = hs[t];
        const bool  inc = (ht >= hprev);
        hprev = ht;
        const float c2  = inc ? 0.5f : -0.5f;
        float acc = 0.f;
        #pragma unroll
        for (int p = 0; p < PPT; p++) {
            const float thr = inc ? na2[p] : nb2[p];
            const float u   = tanh_fast(fmaf(ht, 500.f, thr));
            const float a   = fmaf(-c2, u, 0.5f);
            const float bb  = fmaf(0.5f, u, c2);
            s[p] = fmaf(a, s[p], bb);
            acc  = fmaf(d[p], s[p], acc);
        }
        #pragma unroll
        for (int o = 16; o; o >>= 1) acc += __shfl_xor_sync(0xffffffffu, acc, o);
        if (lane == 0) mypart[t] = acc;
    }
}

// ---------------------------------------------------------------------------
// Kernel 6: reduce warp partials -> m, b_norm
// ---------------------------------------------------------------------------
__global__ __launch_bounds__(256) void finalize_kernel(float* __restrict__ out)
{
    const int idx = blockIdx.x * blockDim.x + threadIdx.x;
    if (idx >= B * T) return;
    const int b = idx / T;
    const int t = idx - b * T;
    const float* p = g_part + (size_t)b * NW2 * T + t;
    float s0 = 0.f, s1 = 0.f;
    #pragma unroll 2
    for (int wv = 0; wv < NW2; wv += 2) {
        s0 += p[(size_t)wv * T];
        s1 += p[(size_t)(wv + 1) * T];
    }
    const float m = (s0 + s1) * g_inv_sum;
    out[OFF_BNORM + idx] = fmaf(0.5f, m, 0.5f);
    out[OFF_M + idx]     = m;
}

// ---------------------------------------------------------------------------
// Kernel 7: broadcast / passthrough
// ---------------------------------------------------------------------------
__global__ __launch_bounds__(256) void fill_kernel(
    const float* __restrict__ s0_all, const float* __restrict__ mesh,
    float* __restrict__ out)
{
    const int i = blockIdx.x * blockDim.x + threadIdx.x;
    if (i < B * NROWS) {
        out[OFF_DENSB + i] = g_density[i % NROWS];
        out[OFF_IS + i]    = s0_all[i];
    }
    if (i < B * NROWS * 2)
        out[OFF_MESHB + i] = mesh[i % (2 * NROWS)];
}

// ---------------------------------------------------------------------------
extern "C" void kernel_launch(void* const* d_in, const int* in_sizes, int n_in,
                              void* d_out, int out_size)
{
    (void)in_sizes; (void)n_in; (void)out_size;
    const float* dec  = (const float*)d_in[1];
    const float* init = (const float*)d_in[2];
    const float* y0   = (const float*)d_in[3];
    const float* mesh = (const float*)d_in[4];
    const float* Win  = (const float*)d_in[5];
    const float* bin  = (const float*)d_in[6];
    const float* Wblk = (const float*)d_in[7];
    const float* bblk = (const float*)d_in[8];
    const float* Wout = (const float*)d_in[9];
    const float* bout = (const float*)d_in[10];
    float* out = (float*)d_out;

    density_kernel<<<DB_BLKS, HID>>>(mesh, Win, bin, Wblk, bblk, Wout, bout);
    pass1_kernel<<<dim3(P1_BLK, C - 1, B), P1_TPB>>>(dec, y0, mesh);
    sum_kernel<<<1, 1024>>>();
    fill_kernel<<<(B * NROWS * 2 + 255) / 256, 256>>>(init, mesh, out);
    compose_kernel<<<(B * NROWS + 255) / 256, 256>>>(init);
    pass2_kernel<<<dim3(P2_BLK, C, B), P2_TPB>>>(dec, y0, mesh);
    finalize_kernel<<<(B * T + 255) / 256, 256>>>(out);
}